// round 1
// baseline (speedup 1.0000x reference)
#include <cuda_runtime.h>
#include <math.h>

// Problem constants
#define NB 32      // batch
#define NP 196     // spatial positions 14*14
#define ND 256     // DENC
#define NE 512     // embed dim
#define NH 512     // hidden
#define NV 30000   // vocab
#define NA 256     // attention dim
#define NT 20      // timesteps
#define KX 1280    // 512 emb + 256 ctx + 512 h
#define G4 2048    // 4*H gates

// -------- device scratch (no allocations allowed) --------
__device__ float g_att1[NB*NP*NA];     // enc @ W_enc + b   [32,196,256]
__device__ float g_xh[NB*KX];          // per-batch [emb(512) | ctx(256) | h(512)]
__device__ float g_c[NB*NH];           // cell state
__device__ float g_gp[20*NB*G4];       // gate partials: 20 k-chunks x [32,2048]
__device__ float g_Hall[NB*NT*NH];     // all hidden states, row m = b*20+t

__device__ __forceinline__ float sigm(float x){ return 1.f/(1.f+__expf(-x)); }

// ================= att1 = enc @ W_enc + b_enc  (M=6272,K=256,N=256) ==========
__global__ __launch_bounds__(256) void k_att1(const float* __restrict__ enc,
                                              const float* __restrict__ W,
                                              const float* __restrict__ bias){
    __shared__ float As[16][68];
    __shared__ float Bs[16][68];
    int bm = blockIdx.x*64, bn = blockIdx.y*64;
    int tid = threadIdx.x;
    int tx = tid & 15, ty = tid >> 4;
    float acc[4][4];
    #pragma unroll
    for (int i=0;i<4;i++)
        #pragma unroll
        for (int j=0;j<4;j++) acc[i][j]=0.f;

    for (int k0 = 0; k0 < 256; k0 += 16){
        {
            int r = tid >> 2, cs = (tid & 3) << 2;
            float4 v = *reinterpret_cast<const float4*>(&enc[(bm+r)*256 + k0 + cs]);
            As[cs+0][r]=v.x; As[cs+1][r]=v.y; As[cs+2][r]=v.z; As[cs+3][r]=v.w;
            int rb = tid >> 4, cb = (tid & 15) << 2;
            *reinterpret_cast<float4*>(&Bs[rb][cb]) =
                *reinterpret_cast<const float4*>(&W[(k0+rb)*256 + bn + cb]);
        }
        __syncthreads();
        #pragma unroll
        for (int kk=0;kk<16;kk++){
            float a[4], b[4];
            #pragma unroll
            for (int i=0;i<4;i++) a[i]=As[kk][ty*4+i];
            #pragma unroll
            for (int j=0;j<4;j++) b[j]=Bs[kk][tx*4+j];
            #pragma unroll
            for (int i=0;i<4;i++)
                #pragma unroll
                for (int j=0;j<4;j++) acc[i][j] += a[i]*b[j];
        }
        __syncthreads();
    }
    #pragma unroll
    for (int i=0;i<4;i++){
        int row = bm + ty*4 + i;
        #pragma unroll
        for (int j=0;j<4;j++){
            int col = bn + tx*4 + j;
            g_att1[row*256 + col] = acc[i][j] + bias[col];
        }
    }
}

// ====== per-step fused kernel: LSTM-update(t-1) + attention(t) + x build =====
// grid = 32 blocks (one per batch element), 256 threads.
// t==20 means "final LSTM update only".
__global__ __launch_bounds__(256) void k_step(int t,
        const float* __restrict__ enc,
        const float* __restrict__ Wd,   // W_dec_att [512,256]
        const float* __restrict__ bd,
        const float* __restrict__ Wfull,
        const float* __restrict__ emb,
        const int*   __restrict__ caps,
        const float* __restrict__ b_ih,
        const float* __restrict__ b_hh){
    int b = blockIdx.x, tid = threadIdx.x;
    __shared__ float h_s[512];
    __shared__ float att2_s[256];
    __shared__ float wf_s[256];
    __shared__ float e_s[200];
    __shared__ float red1[8];
    __shared__ float red2[8];

    // ---- phase 1: LSTM update for step t-1 (or zero init at t==0) ----
    if (t == 0){
        for (int k=tid;k<512;k+=256){
            h_s[k]=0.f; g_c[b*512+k]=0.f; g_xh[b*KX+768+k]=0.f;
        }
    } else {
        for (int k=tid;k<512;k+=256){
            float gi=b_ih[k]       + b_hh[k];
            float gf=b_ih[512+k]   + b_hh[512+k];
            float gg=b_ih[1024+k]  + b_hh[1024+k];
            float go=b_ih[1536+k]  + b_hh[1536+k];
            #pragma unroll 5
            for (int ch=0; ch<20; ch++){
                const float* gp = &g_gp[(ch*32+b)*2048];
                gi += gp[k]; gf += gp[512+k]; gg += gp[1024+k]; go += gp[1536+k];
            }
            float co = g_c[b*512+k];
            float cn = sigm(gf)*co + sigm(gi)*tanhf(gg);
            float hn = sigm(go)*tanhf(cn);
            g_c[b*512+k]=cn;
            h_s[k]=hn;
            g_xh[b*KX+768+k]=hn;
            g_Hall[(b*20 + (t-1))*512 + k]=hn;
        }
    }
    if (t == 20) return;

    // ---- embedding gather for this step ----
    {
        int cap = caps[b*20+t];
        const float* er = &emb[cap*512];
        for (int k=tid;k<512;k+=256) g_xh[b*KX+k] = er[k];
    }
    wf_s[tid] = Wfull[tid];
    __syncthreads();

    // ---- att2 = h @ W_dec + b_dec (one output per thread) ----
    {
        float a0=0.f,a1=0.f,a2=0.f,a3=0.f;
        #pragma unroll 4
        for (int k=0;k<512;k+=4){
            a0 += h_s[k+0]*Wd[(k+0)*256+tid];
            a1 += h_s[k+1]*Wd[(k+1)*256+tid];
            a2 += h_s[k+2]*Wd[(k+2)*256+tid];
            a3 += h_s[k+3]*Wd[(k+3)*256+tid];
        }
        att2_s[tid] = (a0+a1)+(a2+a3) + bd[tid];
    }
    __syncthreads();

    // ---- e[p] = tanh(att1[p]+att2) . W_full  (warp per p) ----
    int wid = tid>>5, lane = tid&31;
    for (int p = wid; p < 196; p += 8){
        const float* ap = &g_att1[(b*196+p)*256];
        float acc = 0.f;
        #pragma unroll
        for (int i=0;i<8;i++){
            int a = lane + i*32;
            acc += tanhf(ap[a] + att2_s[a]) * wf_s[a];
        }
        #pragma unroll
        for (int o=16;o;o>>=1) acc += __shfl_xor_sync(0xffffffffu, acc, o);
        if (lane==0) e_s[p] = acc;
    }
    __syncthreads();

    // ---- softmax over 196 ----
    float v = (tid<196) ? e_s[tid] : -3.4e38f;
    float mx = v;
    #pragma unroll
    for (int o=16;o;o>>=1) mx = fmaxf(mx, __shfl_xor_sync(0xffffffffu, mx, o));
    if (lane==0) red1[wid]=mx;
    __syncthreads();
    if (tid==0){
        float mm = red1[0];
        #pragma unroll
        for (int i=1;i<8;i++) mm = fmaxf(mm, red1[i]);
        red1[0]=mm;
    }
    __syncthreads();
    float gmax = red1[0];
    float ex = (tid<196) ? __expf(v - gmax) : 0.f;
    float s = ex;
    #pragma unroll
    for (int o=16;o;o>>=1) s += __shfl_xor_sync(0xffffffffu, s, o);
    if (lane==0) red2[wid]=s;
    __syncthreads();
    if (tid==0){
        float ss = 0.f;
        #pragma unroll
        for (int i=0;i<8;i++) ss += red2[i];
        red2[0]=ss;
    }
    __syncthreads();
    float inv = 1.f/red2[0];
    if (tid<196) e_s[tid] = ex*inv;
    __syncthreads();

    // ---- context[d] = sum_p alpha[p]*enc[b,p,d]  (thread per d) ----
    {
        const float* eb = &enc[b*196*256 + tid];
        float c0=0.f, c1=0.f;
        for (int p=0;p<196;p+=2){
            c0 += e_s[p]  *eb[(p)  *256];
            c1 += e_s[p+1]*eb[(p+1)*256];
        }
        g_xh[b*KX+512+tid] = c0+c1;
    }
}

// ===== gates partial GEMM: [32,64kchunk] @ W[64,2048-slice] -> g_gp =========
// grid (8 jblocks x 20 kchunks), 256 threads. Chunks 0..11 -> W_ih, 12..19 -> W_hh.
__global__ __launch_bounds__(256) void k_gates(const float* __restrict__ W_ih,
                                               const float* __restrict__ W_hh){
    __shared__ float x_s[64][32];
    int bj = blockIdx.x << 8;          // column base (0..1792)
    int ck = blockIdx.y;               // k-chunk index
    int k0 = ck << 6;
    int tid = threadIdx.x;

    #pragma unroll
    for (int i=0;i<8;i++){
        int idx = tid + (i<<8);
        int bb = idx >> 6, kk = idx & 63;
        x_s[kk][bb] = g_xh[bb*KX + k0 + kk];
    }
    __syncthreads();

    const float* Wbase = (k0 < 768) ? (W_ih + (size_t)k0*2048)
                                    : (W_hh + (size_t)(k0-768)*2048);
    int rg = tid >> 6, cg = tid & 63;
    const float* wp = Wbase + bj + (cg<<2);

    float acc[8][4];
    #pragma unroll
    for (int r=0;r<8;r++)
        #pragma unroll
        for (int c=0;c<4;c++) acc[r][c]=0.f;

    #pragma unroll 4
    for (int kk=0;kk<64;kk++){
        float4 w  = *reinterpret_cast<const float4*>(wp + (size_t)kk*2048);
        float4 xa = *reinterpret_cast<const float4*>(&x_s[kk][rg<<3]);
        float4 xb = *reinterpret_cast<const float4*>(&x_s[kk][(rg<<3)+4]);
        float xr[8] = {xa.x,xa.y,xa.z,xa.w,xb.x,xb.y,xb.z,xb.w};
        #pragma unroll
        for (int r=0;r<8;r++){
            acc[r][0] += xr[r]*w.x;
            acc[r][1] += xr[r]*w.y;
            acc[r][2] += xr[r]*w.z;
            acc[r][3] += xr[r]*w.w;
        }
    }
    #pragma unroll
    for (int r=0;r<8;r++){
        int bb = (rg<<3) + r;
        float4 o = make_float4(acc[r][0],acc[r][1],acc[r][2],acc[r][3]);
        *reinterpret_cast<float4*>(&g_gp[(ck*32+bb)*2048 + bj + (cg<<2)]) = o;
    }
}

// ====== final projection: out[640,30000] = Hall[640,512] @ W_fc + b_fc ======
// BM=BN=128, BK=8, 256 threads, 8x8 microtiles. grid (5, 235).
__global__ __launch_bounds__(256) void k_fc(const float* __restrict__ Wfc,
                                            const float* __restrict__ bfc,
                                            float* __restrict__ out){
    __shared__ float As[8][132];
    __shared__ float Bs[8][132];
    int bm = blockIdx.x << 7;
    int bn = blockIdx.y << 7;
    int tid = threadIdx.x;
    int tx = tid & 15, ty = tid >> 4;

    float acc[8][8];
    #pragma unroll
    for (int i=0;i<8;i++)
        #pragma unroll
        for (int j=0;j<8;j++) acc[i][j]=0.f;

    for (int k0=0;k0<512;k0+=8){
        {
            int r = tid >> 1, h4 = (tid & 1) << 2;
            float4 v = *reinterpret_cast<const float4*>(&g_Hall[(bm+r)*512 + k0 + h4]);
            As[h4+0][r]=v.x; As[h4+1][r]=v.y; As[h4+2][r]=v.z; As[h4+3][r]=v.w;

            int rb = tid >> 5, c4 = (tid & 31) << 2;
            int col = bn + c4;
            float4 w;
            if (col + 3 < NV){
                w = *reinterpret_cast<const float4*>(&Wfc[(size_t)(k0+rb)*NV + col]);
            } else {
                w.x = (col+0<NV)?Wfc[(size_t)(k0+rb)*NV+col+0]:0.f;
                w.y = (col+1<NV)?Wfc[(size_t)(k0+rb)*NV+col+1]:0.f;
                w.z = (col+2<NV)?Wfc[(size_t)(k0+rb)*NV+col+2]:0.f;
                w.w = (col+3<NV)?Wfc[(size_t)(k0+rb)*NV+col+3]:0.f;
            }
            *reinterpret_cast<float4*>(&Bs[rb][c4]) = w;
        }
        __syncthreads();
        #pragma unroll
        for (int kk=0;kk<8;kk++){
            float a[8], bb[8];
            *reinterpret_cast<float4*>(a)    = *reinterpret_cast<const float4*>(&As[kk][ty<<3]);
            *reinterpret_cast<float4*>(a+4)  = *reinterpret_cast<const float4*>(&As[kk][(ty<<3)+4]);
            *reinterpret_cast<float4*>(bb)   = *reinterpret_cast<const float4*>(&Bs[kk][tx<<3]);
            *reinterpret_cast<float4*>(bb+4) = *reinterpret_cast<const float4*>(&Bs[kk][(tx<<3)+4]);
            #pragma unroll
            for (int i=0;i<8;i++)
                #pragma unroll
                for (int j=0;j<8;j++) acc[i][j] += a[i]*bb[j];
        }
        __syncthreads();
    }
    #pragma unroll
    for (int i=0;i<8;i++){
        int row = bm + (ty<<3) + i;
        #pragma unroll
        for (int j=0;j<8;j+=4){
            int col = bn + (tx<<3) + j;
            if (col + 3 < NV){
                float4 bb = *reinterpret_cast<const float4*>(&bfc[col]);
                float4 o = make_float4(acc[i][j]+bb.x, acc[i][j+1]+bb.y,
                                       acc[i][j+2]+bb.z, acc[i][j+3]+bb.w);
                *reinterpret_cast<float4*>(&out[(size_t)row*NV + col]) = o;
            } else {
                #pragma unroll
                for (int q=0;q<4;q++)
                    if (col+q < NV) out[(size_t)row*NV + col + q] = acc[i][j+q] + bfc[col+q];
            }
        }
    }
}

// ============================== launch =======================================
extern "C" void kernel_launch(void* const* d_in, const int* in_sizes, int n_in,
                              void* d_out, int out_size){
    const float* enc    = (const float*)d_in[0];
    const int*   caps   = (const int*)  d_in[1];
    const float* W_enc  = (const float*)d_in[2];
    const float* b_enc  = (const float*)d_in[3];
    const float* W_dec  = (const float*)d_in[4];
    const float* b_dec  = (const float*)d_in[5];
    const float* W_full = (const float*)d_in[6];
    // d_in[7] = b_full: softmax is shift-invariant, unused
    const float* emb    = (const float*)d_in[8];
    const float* W_ih   = (const float*)d_in[9];
    const float* b_ih   = (const float*)d_in[10];
    const float* W_hh   = (const float*)d_in[11];
    const float* b_hh   = (const float*)d_in[12];
    const float* W_fc   = (const float*)d_in[13];
    const float* b_fc   = (const float*)d_in[14];
    float* out = (float*)d_out;

    k_att1<<<dim3(98,4),256>>>(enc, W_enc, b_enc);
    for (int t=0;t<20;t++){
        k_step<<<32,256>>>(t, enc, W_dec, b_dec, W_full, emb, caps, b_ih, b_hh);
        k_gates<<<dim3(8,20),256>>>(W_ih, W_hh);
    }
    k_step<<<32,256>>>(20, enc, W_dec, b_dec, W_full, emb, caps, b_ih, b_hh);
    k_fc<<<dim3(5,235),256>>>(W_fc, b_fc, out);
}

// round 3
// speedup vs baseline: 1.1922x; 1.1922x over previous
#include <cuda_runtime.h>
#include <cuda_bf16.h>
#include <math.h>
#include <stdint.h>

// Problem constants
#define NB 32
#define NP 196
#define ND 256
#define NE 512
#define NH 512
#define NV 30000
#define NA 256
#define NT 20
#define KX 1280     // emb 512 | ctx 256 | h 512
#define G4 2048
#define NCH 10      // gate k-chunks of 128

// -------- device scratch --------
__device__ float g_att1[NB*NP*NA];
__device__ float g_xh[NB*KX];
__device__ float g_c[NB*NH];
__device__ float g_gp[NCH*NB*G4];
__device__ float g_att2[NB*NA];
__device__ float g_e[NB*NP];
__device__ __nv_bfloat16 g_Ahi[NB*NT*NH];       // h rows bf16 hi
__device__ __nv_bfloat16 g_Alo[NB*NT*NH];       // residual lo
__device__ __nv_bfloat16 g_Whi[(size_t)NV*NH];  // Wfc^T hi [N,K]
__device__ __nv_bfloat16 g_Wlo[(size_t)NV*NH];  // Wfc^T lo

__device__ __forceinline__ float sigm(float x){ return 1.f/(1.f+__expf(-x)); }
__device__ __forceinline__ float tanh_fast(float x){
    float y; asm("tanh.approx.f32 %0, %1;" : "=f"(y) : "f"(x)); return y;
}

// ============ convert W_fc [512,30000] fp32 -> transposed bf16 hi/lo [30000,512]
__global__ __launch_bounds__(256) void k_convW(const float* __restrict__ Wfc){
    __shared__ float s[32][33];
    int n0 = blockIdx.x * 32, k0 = blockIdx.y * 32;
    int tx = threadIdx.x & 31, ty = threadIdx.x >> 5;
    #pragma unroll
    for (int i=0;i<4;i++){
        int r = ty + i*8;
        int n = n0 + tx;
        s[r][tx] = (n < NV) ? Wfc[(size_t)(k0+r)*NV + n] : 0.f;
    }
    __syncthreads();
    #pragma unroll
    for (int i=0;i<4;i++){
        int rn = ty + i*8;
        int n = n0 + rn;
        if (n < NV){
            float x = s[tx][rn];
            __nv_bfloat16 hi = __float2bfloat16(x);
            float lo = x - __bfloat162float(hi);
            g_Whi[(size_t)n*NH + k0 + tx] = hi;
            g_Wlo[(size_t)n*NH + k0 + tx] = __float2bfloat16(lo);
        }
    }
}

// ================= att1 = enc @ W_enc + b_enc  (M=6272,K=256,N=256) ==========
__global__ __launch_bounds__(256) void k_att1(const float* __restrict__ enc,
                                              const float* __restrict__ W,
                                              const float* __restrict__ bias){
    __shared__ float As[16][68];
    __shared__ float Bs[16][68];
    int bm = blockIdx.x*64, bn = blockIdx.y*64;
    int tid = threadIdx.x;
    int tx = tid & 15, ty = tid >> 4;
    float acc[4][4];
    #pragma unroll
    for (int i=0;i<4;i++)
        #pragma unroll
        for (int j=0;j<4;j++) acc[i][j]=0.f;
    for (int k0 = 0; k0 < 256; k0 += 16){
        int r = tid >> 2, cs = (tid & 3) << 2;
        float4 v = *reinterpret_cast<const float4*>(&enc[(bm+r)*256 + k0 + cs]);
        As[cs+0][r]=v.x; As[cs+1][r]=v.y; As[cs+2][r]=v.z; As[cs+3][r]=v.w;
        int rb = tid >> 4, cb = (tid & 15) << 2;
        *reinterpret_cast<float4*>(&Bs[rb][cb]) =
            *reinterpret_cast<const float4*>(&W[(k0+rb)*256 + bn + cb]);
        __syncthreads();
        #pragma unroll
        for (int kk=0;kk<16;kk++){
            float a[4], b[4];
            #pragma unroll
            for (int i=0;i<4;i++) a[i]=As[kk][ty*4+i];
            #pragma unroll
            for (int j=0;j<4;j++) b[j]=Bs[kk][tx*4+j];
            #pragma unroll
            for (int i=0;i<4;i++)
                #pragma unroll
                for (int j=0;j<4;j++) acc[i][j] += a[i]*b[j];
        }
        __syncthreads();
    }
    #pragma unroll
    for (int i=0;i<4;i++){
        int row = bm + ty*4 + i;
        #pragma unroll
        for (int j=0;j<4;j++){
            int col = bn + tx*4 + j;
            g_att1[row*256 + col] = acc[i][j] + bias[col];
        }
    }
}

// ====== k_lstm: gate-partial reduce + LSTM update (t-1) + embed(t) ==========
__global__ __launch_bounds__(256) void k_lstm(int t,
        const float* __restrict__ emb, const int* __restrict__ caps,
        const float* __restrict__ b_ih, const float* __restrict__ b_hh){
    int b = blockIdx.x, tid = threadIdx.x;
    if (t == 0){
        for (int k=tid;k<512;k+=256){ g_c[b*512+k]=0.f; g_xh[b*KX+768+k]=0.f; }
    } else {
        for (int k=tid;k<512;k+=256){
            float gi=b_ih[k]      + b_hh[k];
            float gf=b_ih[512+k]  + b_hh[512+k];
            float gg=b_ih[1024+k] + b_hh[1024+k];
            float go=b_ih[1536+k] + b_hh[1536+k];
            #pragma unroll
            for (int ch=0; ch<NCH; ch++){
                const float* gp = &g_gp[(ch*NB+b)*G4];
                gi += gp[k]; gf += gp[512+k]; gg += gp[1024+k]; go += gp[1536+k];
            }
            float co = g_c[b*512+k];
            float cn = sigm(gf)*co + sigm(gi)*tanhf(gg);
            float hn = sigm(go)*tanhf(cn);
            g_c[b*512+k]=cn;
            g_xh[b*KX+768+k]=hn;
            int row = b*NT + (t-1);
            __nv_bfloat16 hi = __float2bfloat16(hn);
            g_Ahi[row*512+k] = hi;
            g_Alo[row*512+k] = __float2bfloat16(hn - __bfloat162float(hi));
        }
    }
    if (t >= NT) return;
    int cap = caps[b*NT+t];
    const float* er = &emb[(size_t)cap*512];
    for (int k=tid;k<512;k+=256) g_xh[b*KX+k] = er[k];
}

// ====== k_att2: att2[32,256] = h[32,512] @ Wd[512,256] + bd ==================
__global__ __launch_bounds__(256) void k_att2(const float* __restrict__ Wd,
                                              const float* __restrict__ bd){
    int col = blockIdx.x*32 + (threadIdx.x & 31);
    int b   = blockIdx.y*8  + (threadIdx.x >> 5);
    const float* hp = &g_xh[b*KX+768];
    float a0=0.f,a1=0.f,a2=0.f,a3=0.f;
    #pragma unroll 4
    for (int k=0;k<512;k+=4){
        a0 += hp[k+0]*Wd[(k+0)*256+col];
        a1 += hp[k+1]*Wd[(k+1)*256+col];
        a2 += hp[k+2]*Wd[(k+2)*256+col];
        a3 += hp[k+3]*Wd[(k+3)*256+col];
    }
    g_att2[b*256+col] = (a0+a1)+(a2+a3) + bd[col];
}

// ====== k_escore: e[b,p] = tanh(att1+att2) . W_full =========================
__global__ __launch_bounds__(128) void k_escore(const float* __restrict__ Wfull){
    __shared__ float att2_s[256];
    __shared__ float wf_s[256];
    int b = blockIdx.x, pg = blockIdx.y;
    int tid = threadIdx.x, wid = tid>>5, lane = tid&31;
    att2_s[tid]     = g_att2[b*256+tid];
    att2_s[tid+128] = g_att2[b*256+tid+128];
    wf_s[tid]       = Wfull[tid];
    wf_s[tid+128]   = Wfull[tid+128];
    __syncthreads();
    #pragma unroll
    for (int j=0;j<7;j++){
        int p = pg*28 + wid*7 + j;
        const float* ap = &g_att1[(b*196+p)*256];
        float acc = 0.f;
        #pragma unroll
        for (int i=0;i<8;i++){
            int a = lane + i*32;
            acc += tanh_fast(ap[a] + att2_s[a]) * wf_s[a];
        }
        #pragma unroll
        for (int o=16;o;o>>=1) acc += __shfl_xor_sync(0xffffffffu, acc, o);
        if (lane==0) g_e[b*196+p] = acc;
    }
}

// ====== k_ctx: softmax(e) + context -> g_xh[512..768] =======================
__global__ __launch_bounds__(256) void k_ctx(const float* __restrict__ enc){
    __shared__ float a_s[200];
    __shared__ float red[8];
    int b = blockIdx.x, tid = threadIdx.x, wid = tid>>5, lane = tid&31;
    float v = (tid<196) ? g_e[b*196+tid] : -3.4e38f;
    float mx = v;
    #pragma unroll
    for (int o=16;o;o>>=1) mx = fmaxf(mx, __shfl_xor_sync(0xffffffffu, mx, o));
    if (lane==0) red[wid]=mx;
    __syncthreads();
    if (tid==0){ float m=red[0];
        #pragma unroll
        for(int i=1;i<8;i++) m=fmaxf(m,red[i]); red[0]=m; }
    __syncthreads();
    float gmax = red[0];
    float ex = (tid<196) ? __expf(v-gmax) : 0.f;
    float s = ex;
    #pragma unroll
    for (int o=16;o;o>>=1) s += __shfl_xor_sync(0xffffffffu, s, o);
    __syncthreads();
    if (lane==0) red[wid]=s;
    __syncthreads();
    if (tid==0){ float ss=0.f;
        #pragma unroll
        for(int i=0;i<8;i++) ss+=red[i]; red[0]=ss; }
    __syncthreads();
    float inv = 1.f/red[0];
    if (tid<196) a_s[tid] = ex*inv;
    if (tid>=196 && tid<200) a_s[tid]=0.f;
    __syncthreads();
    const float* eb = &enc[b*196*256 + tid];
    float c0=0.f,c1=0.f,c2=0.f,c3=0.f;
    #pragma unroll 2
    for (int p=0;p<196;p+=4){
        c0 += a_s[p+0]*eb[(p+0)*256];
        c1 += a_s[p+1]*eb[(p+1)*256];
        c2 += a_s[p+2]*eb[(p+2)*256];
        c3 += a_s[p+3]*eb[(p+3)*256];
    }
    g_xh[b*KX+512+tid] = (c0+c1)+(c2+c3);
}

// ===== k_gates: partial GEMM [32,128] @ W[128,2048-slice] -> g_gp ===========
__global__ __launch_bounds__(256) void k_gates(const float* __restrict__ W_ih,
                                               const float* __restrict__ W_hh){
    __shared__ float x_s[128][33];
    int bj = blockIdx.x << 8;
    int ck = blockIdx.y;
    int k0 = ck << 7;
    int tid = threadIdx.x;
    #pragma unroll
    for (int i=0;i<16;i++){
        int idx = tid + (i<<8);
        int bb = idx >> 7, kk = idx & 127;
        x_s[kk][bb] = g_xh[bb*KX + k0 + kk];
    }
    __syncthreads();
    const float* Wbase = (k0 < 768) ? (W_ih + (size_t)k0*G4)
                                    : (W_hh + (size_t)(k0-768)*G4);
    int rg = tid >> 6, cg = tid & 63;
    const float* wp = Wbase + bj + (cg<<2);
    float acc[8][4];
    #pragma unroll
    for (int r=0;r<8;r++)
        #pragma unroll
        for (int c=0;c<4;c++) acc[r][c]=0.f;
    #pragma unroll 4
    for (int kk=0;kk<128;kk++){
        float4 w = *reinterpret_cast<const float4*>(wp + (size_t)kk*G4);
        #pragma unroll
        for (int r=0;r<8;r++){
            float xr = x_s[kk][(rg<<3)+r];
            acc[r][0] += xr*w.x; acc[r][1] += xr*w.y;
            acc[r][2] += xr*w.z; acc[r][3] += xr*w.w;
        }
    }
    #pragma unroll
    for (int r=0;r<8;r++){
        int bb = (rg<<3) + r;
        float4 o = make_float4(acc[r][0],acc[r][1],acc[r][2],acc[r][3]);
        *reinterpret_cast<float4*>(&g_gp[(ck*NB+bb)*G4 + bj + (cg<<2)]) = o;
    }
}

// ====================== HMMA final projection ===============================
// out[640,30000] = A[640,512] @ W^T + b ; bf16 hi/lo 3-pass via mma.sync
// block tile 128x128, BK=32, 8 warps (warp tile 64x32)
__device__ __forceinline__ uint32_t smem_u32(const void* p){
    uint32_t a;
    asm("{ .reg .u64 t; cvta.to.shared.u64 t, %1; cvt.u32.u64 %0, t; }" : "=r"(a) : "l"(p));
    return a;
}
__device__ __forceinline__ void ldsm4(uint32_t &r0,uint32_t &r1,uint32_t &r2,uint32_t &r3,
                                      uint32_t addr){
    asm volatile("ldmatrix.sync.aligned.m8n8.x4.shared.b16 {%0,%1,%2,%3}, [%4];"
        : "=r"(r0),"=r"(r1),"=r"(r2),"=r"(r3) : "r"(addr));
}
__device__ __forceinline__ void mma_bf16(float* d, const uint32_t* a, const uint32_t* b){
    asm volatile("mma.sync.aligned.m16n8k16.row.col.f32.bf16.bf16.f32 "
        "{%0,%1,%2,%3}, {%4,%5,%6,%7}, {%8,%9}, {%0,%1,%2,%3};"
        : "+f"(d[0]),"+f"(d[1]),"+f"(d[2]),"+f"(d[3])
        : "r"(a[0]),"r"(a[1]),"r"(a[2]),"r"(a[3]), "r"(b[0]),"r"(b[1]));
}

__global__ __launch_bounds__(256) void k_fc_mma(const float* __restrict__ bfc,
                                                float* __restrict__ out){
    __shared__ __align__(128) char sAh[128*64];
    __shared__ __align__(128) char sAl[128*64];
    __shared__ __align__(128) char sBh[128*64];
    __shared__ __align__(128) char sBl[128*64];
    int tid = threadIdx.x, wid = tid>>5, lane = tid&31;
    int bm = blockIdx.x << 7, bn = blockIdx.y << 7;
    int wm = (wid>>2)*64, wn = (wid&3)*32;

    float acc[4][4][4];
    #pragma unroll
    for (int i=0;i<4;i++)
        #pragma unroll
        for (int j=0;j<4;j++)
            #pragma unroll
            for (int q=0;q<4;q++) acc[i][j][q]=0.f;

    // gmem->smem mapping: thread loads 2 consecutive 16B chunks of one row
    int crow = tid >> 1;
    int cch  = (tid & 1) * 2;
    int nrow = bn + crow;
    bool nok = (nrow < NV);
    const uint4 zero4 = make_uint4(0,0,0,0);

    uint32_t aAh = smem_u32(sAh), aAl = smem_u32(sAl);
    uint32_t aBh = smem_u32(sBh), aBl = smem_u32(sBl);

    // precompute ldmatrix lane addresses (byte offsets within tile)
    // A: row = (lane&7) + ((lane>>3)&1)*8 ; chunk-half = lane>>4
    int ar = (lane&7) + ((lane>>3)&1)*8;
    int ah = lane>>4;
    // B: row = (lane&7) + (lane>>4)*8 ; chunk-half = (lane>>3)&1
    int br = (lane&7) + (lane>>4)*8;
    int bh = (lane>>3)&1;

    for (int step=0; step<16; step++){
        int k0 = step << 5;
        {
            const uint4* gah = reinterpret_cast<const uint4*>(&g_Ahi[(bm+crow)*512 + k0]);
            const uint4* gal = reinterpret_cast<const uint4*>(&g_Alo[(bm+crow)*512 + k0]);
            const uint4* gwh = reinterpret_cast<const uint4*>(&g_Whi[(size_t)nrow*512 + k0]);
            const uint4* gwl = reinterpret_cast<const uint4*>(&g_Wlo[(size_t)nrow*512 + k0]);
            #pragma unroll
            for (int j=0;j<2;j++){
                int ch = cch + j;
                uint32_t sw = crow*64 + ((ch ^ (crow&3))<<4);
                *reinterpret_cast<uint4*>(sAh + sw) = gah[ch];
                *reinterpret_cast<uint4*>(sAl + sw) = gal[ch];
                *reinterpret_cast<uint4*>(sBh + sw) = nok ? gwh[ch] : zero4;
                *reinterpret_cast<uint4*>(sBl + sw) = nok ? gwl[ch] : zero4;
            }
        }
        __syncthreads();
        #pragma unroll
        for (int kk=0;kk<2;kk++){
            uint32_t fAh[4][4], fAl[4][4];
            uint32_t fBh[4][2], fBl[4][2];
            #pragma unroll
            for (int mt=0;mt<4;mt++){
                int row = wm + mt*16 + ar;
                int ch = kk*2 + ah;
                uint32_t off = row*64 + ((ch ^ (row&3))<<4);
                ldsm4(fAh[mt][0],fAh[mt][1],fAh[mt][2],fAh[mt][3], aAh + off);
                ldsm4(fAl[mt][0],fAl[mt][1],fAl[mt][2],fAl[mt][3], aAl + off);
            }
            #pragma unroll
            for (int nt2=0;nt2<2;nt2++){
                int row = wn + nt2*16 + br;
                int ch = kk*2 + bh;
                uint32_t off = row*64 + ((ch ^ (row&3))<<4);
                uint32_t r0,r1,r2,r3;
                ldsm4(r0,r1,r2,r3, aBh + off);
                fBh[nt2*2][0]=r0; fBh[nt2*2][1]=r1; fBh[nt2*2+1][0]=r2; fBh[nt2*2+1][1]=r3;
                ldsm4(r0,r1,r2,r3, aBl + off);
                fBl[nt2*2][0]=r0; fBl[nt2*2][1]=r1; fBl[nt2*2+1][0]=r2; fBl[nt2*2+1][1]=r3;
            }
            #pragma unroll
            for (int mt=0;mt<4;mt++)
                #pragma unroll
                for (int nt=0;nt<4;nt++){
                    mma_bf16(acc[mt][nt], fAh[mt], fBh[nt]);
                    mma_bf16(acc[mt][nt], fAh[mt], fBl[nt]);
                    mma_bf16(acc[mt][nt], fAl[mt], fBh[nt]);
                }
        }
        __syncthreads();
    }

    // epilogue
    #pragma unroll
    for (int mt=0;mt<4;mt++){
        int row = bm + wm + mt*16 + (lane>>2);
        #pragma unroll
        for (int nt=0;nt<4;nt++){
            int col = bn + wn + nt*8 + (lane&3)*2;
            if (col < NV){
                float2 bb = *reinterpret_cast<const float2*>(&bfc[col]);
                float2 o0 = make_float2(acc[mt][nt][0]+bb.x, acc[mt][nt][1]+bb.y);
                float2 o1 = make_float2(acc[mt][nt][2]+bb.x, acc[mt][nt][3]+bb.y);
                *reinterpret_cast<float2*>(&out[(size_t)row*NV + col]) = o0;
                *reinterpret_cast<float2*>(&out[(size_t)(row+8)*NV + col]) = o1;
            }
        }
    }
}

// ============================== launch =======================================
extern "C" void kernel_launch(void* const* d_in, const int* in_sizes, int n_in,
                              void* d_out, int out_size){
    const float* enc    = (const float*)d_in[0];
    const int*   caps   = (const int*)  d_in[1];
    const float* W_enc  = (const float*)d_in[2];
    const float* b_enc  = (const float*)d_in[3];
    const float* W_dec  = (const float*)d_in[4];
    const float* b_dec  = (const float*)d_in[5];
    const float* W_full = (const float*)d_in[6];
    const float* emb    = (const float*)d_in[8];
    const float* W_ih   = (const float*)d_in[9];
    const float* b_ih   = (const float*)d_in[10];
    const float* W_hh   = (const float*)d_in[11];
    const float* b_hh   = (const float*)d_in[12];
    const float* W_fc   = (const float*)d_in[13];
    const float* b_fc   = (const float*)d_in[14];
    float* out = (float*)d_out;

    k_convW<<<dim3(938,16),256>>>(W_fc);
    k_att1<<<dim3(98,4),256>>>(enc, W_enc, b_enc);
    for (int t=0;t<NT;t++){
        k_lstm<<<32,256>>>(t, emb, caps, b_ih, b_hh);
        k_att2<<<dim3(8,4),256>>>(W_dec, b_dec);
        k_escore<<<dim3(32,7),128>>>(W_full);
        k_ctx<<<32,256>>>(enc);
        k_gates<<<dim3(8,10),256>>>(W_ih, W_hh);
    }
    k_lstm<<<32,256>>>(NT, emb, caps, b_ih, b_hh);
    k_fc_mma<<<dim3(5,235),256>>>(b_fc, out);
}

// round 7
// speedup vs baseline: 1.6072x; 1.3481x over previous
#include <cuda_runtime.h>
#include <cuda_bf16.h>
#include <math.h>
#include <stdint.h>

// Problem constants
#define NB 32
#define NP 196
#define ND 256
#define NE 512
#define NH 512
#define NV 30000
#define NA 256
#define NT 20
#define KX 1280     // emb 512 | ctx 256 | h 512
#define G4 2048
#define NCH 20      // gate k-chunks of 64

// -------- device scratch --------
__device__ float g_att1[NB*NP*NA];
__device__ float g_xh[NB*KX];
__device__ float g_c[NB*NH];
__device__ float g_gp[NCH*NB*G4];
__device__ float g_att2p[8*NB*NA];              // k-split att2 partials
__device__ float g_e[NB*NP];
__device__ __nv_bfloat16 g_Ahi[NB*NT*NH];       // h rows bf16 hi
__device__ __nv_bfloat16 g_Alo[NB*NT*NH];       // residual lo
__device__ __nv_bfloat16 g_Whi[(size_t)NV*NH];  // Wfc^T hi [N,K]
__device__ __nv_bfloat16 g_Wlo[(size_t)NV*NH];  // Wfc^T lo

__device__ __forceinline__ float sigm(float x){ return 1.f/(1.f+__expf(-x)); }
__device__ __forceinline__ float tanh_fast(float x){
    float y; asm("tanh.approx.f32 %0, %1;" : "=f"(y) : "f"(x)); return y;
}

// ============ convert W_fc [512,30000] fp32 -> transposed bf16 hi/lo [30000,512]
__global__ __launch_bounds__(256) void k_convW(const float* __restrict__ Wfc){
    __shared__ float s[32][33];
    int n0 = blockIdx.x * 32, k0 = blockIdx.y * 32;
    int tx = threadIdx.x & 31, ty = threadIdx.x >> 5;
    #pragma unroll
    for (int i=0;i<4;i++){
        int r = ty + i*8;
        int n = n0 + tx;
        s[r][tx] = (n < NV) ? Wfc[(size_t)(k0+r)*NV + n] : 0.f;
    }
    __syncthreads();
    #pragma unroll
    for (int i=0;i<4;i++){
        int rn = ty + i*8;
        int n = n0 + rn;
        if (n < NV){
            float x = s[tx][rn];
            __nv_bfloat16 hi = __float2bfloat16(x);
            float lo = x - __bfloat162float(hi);
            g_Whi[(size_t)n*NH + k0 + tx] = hi;
            g_Wlo[(size_t)n*NH + k0 + tx] = __float2bfloat16(lo);
        }
    }
}

// ================= att1 = enc @ W_enc + b_enc  (M=6272,K=256,N=256) ==========
__global__ __launch_bounds__(256) void k_att1(const float* __restrict__ enc,
                                              const float* __restrict__ W,
                                              const float* __restrict__ bias){
    __shared__ float As[16][68];
    __shared__ float Bs[16][68];
    int bm = blockIdx.x*64, bn = blockIdx.y*64;
    int tid = threadIdx.x;
    int tx = tid & 15, ty = tid >> 4;
    float acc[4][4];
    #pragma unroll
    for (int i=0;i<4;i++)
        #pragma unroll
        for (int j=0;j<4;j++) acc[i][j]=0.f;
    for (int k0 = 0; k0 < 256; k0 += 16){
        int r = tid >> 2, cs = (tid & 3) << 2;
        float4 v = *reinterpret_cast<const float4*>(&enc[(bm+r)*256 + k0 + cs]);
        As[cs+0][r]=v.x; As[cs+1][r]=v.y; As[cs+2][r]=v.z; As[cs+3][r]=v.w;
        int rb = tid >> 4, cb = (tid & 15) << 2;
        *reinterpret_cast<float4*>(&Bs[rb][cb]) =
            *reinterpret_cast<const float4*>(&W[(k0+rb)*256 + bn + cb]);
        __syncthreads();
        #pragma unroll
        for (int kk=0;kk<16;kk++){
            float a[4], b[4];
            #pragma unroll
            for (int i=0;i<4;i++) a[i]=As[kk][ty*4+i];
            #pragma unroll
            for (int j=0;j<4;j++) b[j]=Bs[kk][tx*4+j];
            #pragma unroll
            for (int i=0;i<4;i++)
                #pragma unroll
                for (int j=0;j<4;j++) acc[i][j] += a[i]*b[j];
        }
        __syncthreads();
    }
    #pragma unroll
    for (int i=0;i<4;i++){
        int row = bm + ty*4 + i;
        #pragma unroll
        for (int j=0;j<4;j++){
            int col = bn + tx*4 + j;
            g_att1[row*256 + col] = acc[i][j] + bias[col];
        }
    }
}

// ====== k_lstm: gate-partial reduce + LSTM update (t-1) + embed(t) ==========
__global__ __launch_bounds__(256) void k_lstm(int t,
        const float* __restrict__ emb, const int* __restrict__ caps,
        const float* __restrict__ b_ih, const float* __restrict__ b_hh){
    int b = blockIdx.x, tid = threadIdx.x;
    if (t == 0){
        for (int k=tid;k<512;k+=256){ g_c[b*512+k]=0.f; g_xh[b*KX+768+k]=0.f; }
    } else {
        for (int k=tid;k<512;k+=256){
            float gi=b_ih[k]      + b_hh[k];
            float gf=b_ih[512+k]  + b_hh[512+k];
            float gg=b_ih[1024+k] + b_hh[1024+k];
            float go=b_ih[1536+k] + b_hh[1536+k];
            #pragma unroll
            for (int ch=0; ch<NCH; ch++){
                const float* gp = &g_gp[(ch*NB+b)*G4];
                gi += gp[k]; gf += gp[512+k]; gg += gp[1024+k]; go += gp[1536+k];
            }
            float co = g_c[b*512+k];
            float cn = sigm(gf)*co + sigm(gi)*tanhf(gg);
            float hn = sigm(go)*tanhf(cn);
            g_c[b*512+k]=cn;
            g_xh[b*KX+768+k]=hn;
            int row = b*NT + (t-1);
            __nv_bfloat16 hi = __float2bfloat16(hn);
            g_Ahi[row*512+k] = hi;
            g_Alo[row*512+k] = __float2bfloat16(hn - __bfloat162float(hi));
        }
    }
    if (t >= NT) return;
    int cap = caps[b*NT+t];
    const float* er = &emb[(size_t)cap*512];
    for (int k=tid;k<512;k+=256) g_xh[b*KX+k] = er[k];
}

// ====== k_att2p: k-split partials of att2 = h @ Wd ==========================
// grid (8 colgroups, 8 kchunks, 4 bgroups), 256 thr = (32 col, 8 b)
__global__ __launch_bounds__(256) void k_att2p(const float* __restrict__ Wd){
    __shared__ float h_s[8][65];
    int cg = blockIdx.x, kc = blockIdx.y, bg = blockIdx.z;
    int lane = threadIdx.x & 31, bw = threadIdx.x >> 5;
    int col = cg*32 + lane;
    int k0 = kc*64;
    {
        int u = threadIdx.x;
        #pragma unroll
        for (int i=0;i<2;i++){
            int v = u + i*256;
            int bb = v >> 6, kk = v & 63;
            h_s[bb][kk] = g_xh[(bg*8+bb)*KX + 768 + k0 + kk];
        }
    }
    __syncthreads();
    const float* wp = Wd + (size_t)k0*256 + col;
    float a0=0.f,a1=0.f,a2=0.f,a3=0.f;
    #pragma unroll 4
    for (int k=0;k<64;k+=4){
        a0 += h_s[bw][k+0]*wp[(size_t)(k+0)*256];
        a1 += h_s[bw][k+1]*wp[(size_t)(k+1)*256];
        a2 += h_s[bw][k+2]*wp[(size_t)(k+2)*256];
        a3 += h_s[bw][k+3]*wp[(size_t)(k+3)*256];
    }
    g_att2p[kc*(NB*NA) + (bg*8+bw)*256 + col] = (a0+a1)+(a2+a3);
}

// ====== k_escore: e[b,p] = tanh(att1 + Σatt2p + bd) . W_full ================
__global__ __launch_bounds__(128) void k_escore(const float* __restrict__ Wfull,
                                                const float* __restrict__ bd){
    __shared__ float att2_s[256];
    __shared__ float wf_s[256];
    int b = blockIdx.x, pg = blockIdx.y;
    int tid = threadIdx.x, wid = tid>>5, lane = tid&31;
    #pragma unroll
    for (int i=0;i<2;i++){
        int a = tid + i*128;
        float s = bd[a];
        #pragma unroll
        for (int kc=0;kc<8;kc++) s += g_att2p[kc*(NB*NA) + b*256 + a];
        att2_s[a] = s;
        wf_s[a] = Wfull[a];
    }
    __syncthreads();
    #pragma unroll
    for (int j=0;j<7;j++){
        int p = pg*28 + wid*7 + j;
        const float* ap = &g_att1[(b*196+p)*256];
        float acc = 0.f;
        #pragma unroll
        for (int i=0;i<8;i++){
            int a = lane + i*32;
            acc += tanh_fast(ap[a] + att2_s[a]) * wf_s[a];
        }
        #pragma unroll
        for (int o=16;o;o>>=1) acc += __shfl_xor_sync(0xffffffffu, acc, o);
        if (lane==0) g_e[b*196+p] = acc;
    }
}

// ====== k_ctx: softmax(e) + context -> g_xh[512..768] =======================
__global__ __launch_bounds__(256) void k_ctx(const float* __restrict__ enc){
    __shared__ float a_s[200];
    __shared__ float red[8];
    int b = blockIdx.x, tid = threadIdx.x, wid = tid>>5, lane = tid&31;
    float v = (tid<196) ? g_e[b*196+tid] : -3.4e38f;
    float mx = v;
    #pragma unroll
    for (int o=16;o;o>>=1) mx = fmaxf(mx, __shfl_xor_sync(0xffffffffu, mx, o));
    if (lane==0) red[wid]=mx;
    __syncthreads();
    if (tid==0){ float m=red[0];
        #pragma unroll
        for(int i=1;i<8;i++) m=fmaxf(m,red[i]); red[0]=m; }
    __syncthreads();
    float gmax = red[0];
    float ex = (tid<196) ? __expf(v-gmax) : 0.f;
    float s = ex;
    #pragma unroll
    for (int o=16;o;o>>=1) s += __shfl_xor_sync(0xffffffffu, s, o);
    __syncthreads();
    if (lane==0) red[wid]=s;
    __syncthreads();
    if (tid==0){ float ss=0.f;
        #pragma unroll
        for(int i=0;i<8;i++) ss+=red[i]; red[0]=ss; }
    __syncthreads();
    float inv = 1.f/red[0];
    if (tid<196) a_s[tid] = ex*inv;
    if (tid>=196 && tid<200) a_s[tid]=0.f;
    __syncthreads();
    const float* eb = &enc[b*196*256 + tid];
    float c0=0.f,c1=0.f,c2=0.f,c3=0.f;
    #pragma unroll 8
    for (int p=0;p<196;p+=4){
        c0 += a_s[p+0]*eb[(p+0)*256];
        c1 += a_s[p+1]*eb[(p+1)*256];
        c2 += a_s[p+2]*eb[(p+2)*256];
        c3 += a_s[p+3]*eb[(p+3)*256];
    }
    g_xh[b*KX+512+tid] = (c0+c1)+(c2+c3);
}

// ===== k_gates: partial GEMM [32,64] @ W[64,2048-slice] -> g_gp =============
// grid (8 jblocks, 20 kchunks), 256 threads
__global__ __launch_bounds__(256) void k_gates(const float* __restrict__ W_ih,
                                               const float* __restrict__ W_hh){
    __shared__ float x_s[64][33];
    int bj = blockIdx.x << 8;
    int ck = blockIdx.y;
    int k0 = ck << 6;
    int tid = threadIdx.x;
    #pragma unroll
    for (int i=0;i<8;i++){
        int idx = tid + (i<<8);
        int bb = idx >> 6, kk = idx & 63;
        x_s[kk][bb] = g_xh[bb*KX + k0 + kk];
    }
    __syncthreads();
    const float* Wbase = (k0 < 768) ? (W_ih + (size_t)k0*G4)
                                    : (W_hh + (size_t)(k0-768)*G4);
    int rg = tid >> 6, cg = tid & 63;
    const float* wp = Wbase + bj + (cg<<2);
    float acc[8][4];
    #pragma unroll
    for (int r=0;r<8;r++)
        #pragma unroll
        for (int c=0;c<4;c++) acc[r][c]=0.f;
    #pragma unroll 4
    for (int kk=0;kk<64;kk++){
        float4 w = *reinterpret_cast<const float4*>(wp + (size_t)kk*G4);
        #pragma unroll
        for (int r=0;r<8;r++){
            float xr = x_s[kk][(rg<<3)+r];
            acc[r][0] += xr*w.x; acc[r][1] += xr*w.y;
            acc[r][2] += xr*w.z; acc[r][3] += xr*w.w;
        }
    }
    #pragma unroll
    for (int r=0;r<8;r++){
        int bb = (rg<<3) + r;
        float4 o = make_float4(acc[r][0],acc[r][1],acc[r][2],acc[r][3]);
        *reinterpret_cast<float4*>(&g_gp[(ck*NB+bb)*G4 + bj + (cg<<2)]) = o;
    }
}

// ====================== HMMA final projection ===============================
__device__ __forceinline__ uint32_t smem_u32(const void* p){
    uint32_t a;
    asm("{ .reg .u64 t; cvta.to.shared.u64 t, %1; cvt.u32.u64 %0, t; }" : "=r"(a) : "l"(p));
    return a;
}
__device__ __forceinline__ void ldsm4(uint32_t &r0,uint32_t &r1,uint32_t &r2,uint32_t &r3,
                                      uint32_t addr){
    asm volatile("ldmatrix.sync.aligned.m8n8.x4.shared.b16 {%0,%1,%2,%3}, [%4];"
        : "=r"(r0),"=r"(r1),"=r"(r2),"=r"(r3) : "r"(addr));
}
__device__ __forceinline__ void mma_bf16(float* d, const uint32_t* a, const uint32_t* b){
    asm volatile("mma.sync.aligned.m16n8k16.row.col.f32.bf16.bf16.f32 "
        "{%0,%1,%2,%3}, {%4,%5,%6,%7}, {%8,%9}, {%0,%1,%2,%3};"
        : "+f"(d[0]),"+f"(d[1]),"+f"(d[2]),"+f"(d[3])
        : "r"(a[0]),"r"(a[1]),"r"(a[2]),"r"(a[3]), "r"(b[0]),"r"(b[1]));
}

__global__ __launch_bounds__(256) void k_fc_mma(const float* __restrict__ bfc,
                                                float* __restrict__ out){
    __shared__ __align__(128) char sAh[128*64];
    __shared__ __align__(128) char sAl[128*64];
    __shared__ __align__(128) char sBh[128*64];
    __shared__ __align__(128) char sBl[128*64];
    int tid = threadIdx.x, wid = tid>>5, lane = tid&31;
    int bm = blockIdx.x << 7, bn = blockIdx.y << 7;
    int wm = (wid>>2)*64, wn = (wid&3)*32;

    float acc[4][4][4];
    #pragma unroll
    for (int i=0;i<4;i++)
        #pragma unroll
        for (int j=0;j<4;j++)
            #pragma unroll
            for (int q=0;q<4;q++) acc[i][j][q]=0.f;

    int crow = tid >> 1;
    int cch  = (tid & 1) * 2;
    int nrow = bn + crow;
    bool nok = (nrow < NV);
    const uint4 zero4 = make_uint4(0,0,0,0);

    uint32_t aAh = smem_u32(sAh), aAl = smem_u32(sAl);
    uint32_t aBh = smem_u32(sBh), aBl = smem_u32(sBl);

    int ar = (lane&7) + ((lane>>3)&1)*8;
    int ah = lane>>4;
    int br = (lane&7) + (lane>>4)*8;
    int bh = (lane>>3)&1;

    for (int step=0; step<16; step++){
        int k0 = step << 5;
        {
            const uint4* gah = reinterpret_cast<const uint4*>(&g_Ahi[(bm+crow)*512 + k0]);
            const uint4* gal = reinterpret_cast<const uint4*>(&g_Alo[(bm+crow)*512 + k0]);
            const uint4* gwh = reinterpret_cast<const uint4*>(&g_Whi[(size_t)nrow*512 + k0]);
            const uint4* gwl = reinterpret_cast<const uint4*>(&g_Wlo[(size_t)nrow*512 + k0]);
            #pragma unroll
            for (int j=0;j<2;j++){
                int ch = cch + j;
                uint32_t sw = crow*64 + ((ch ^ (crow&3))<<4);
                *reinterpret_cast<uint4*>(sAh + sw) = gah[ch];
                *reinterpret_cast<uint4*>(sAl + sw) = gal[ch];
                *reinterpret_cast<uint4*>(sBh + sw) = nok ? gwh[ch] : zero4;
                *reinterpret_cast<uint4*>(sBl + sw) = nok ? gwl[ch] : zero4;
            }
        }
        __syncthreads();
        #pragma unroll
        for (int kk=0;kk<2;kk++){
            uint32_t fAh[4][4], fAl[4][4];
            uint32_t fBh[4][2], fBl[4][2];
            #pragma unroll
            for (int mt=0;mt<4;mt++){
                int row = wm + mt*16 + ar;
                int ch = kk*2 + ah;
                uint32_t off = row*64 + ((ch ^ (row&3))<<4);
                ldsm4(fAh[mt][0],fAh[mt][1],fAh[mt][2],fAh[mt][3], aAh + off);
                ldsm4(fAl[mt][0],fAl[mt][1],fAl[mt][2],fAl[mt][3], aAl + off);
            }
            #pragma unroll
            for (int nt2=0;nt2<2;nt2++){
                int row = wn + nt2*16 + br;
                int ch = kk*2 + bh;
                uint32_t off = row*64 + ((ch ^ (row&3))<<4);
                uint32_t r0,r1,r2,r3;
                ldsm4(r0,r1,r2,r3, aBh + off);
                fBh[nt2*2][0]=r0; fBh[nt2*2][1]=r1; fBh[nt2*2+1][0]=r2; fBh[nt2*2+1][1]=r3;
                ldsm4(r0,r1,r2,r3, aBl + off);
                fBl[nt2*2][0]=r0; fBl[nt2*2][1]=r1; fBl[nt2*2+1][0]=r2; fBl[nt2*2+1][1]=r3;
            }
            #pragma unroll
            for (int mt=0;mt<4;mt++)
                #pragma unroll
                for (int nt=0;nt<4;nt++){
                    mma_bf16(acc[mt][nt], fAh[mt], fBh[nt]);
                    mma_bf16(acc[mt][nt], fAh[mt], fBl[nt]);
                    mma_bf16(acc[mt][nt], fAl[mt], fBh[nt]);
                }
        }
        __syncthreads();
    }

    #pragma unroll
    for (int mt=0;mt<4;mt++){
        int row = bm + wm + mt*16 + (lane>>2);
        #pragma unroll
        for (int nt=0;nt<4;nt++){
            int col = bn + wn + nt*8 + (lane&3)*2;
            if (col < NV){
                float2 bb = *reinterpret_cast<const float2*>(&bfc[col]);
                float2 o0 = make_float2(acc[mt][nt][0]+bb.x, acc[mt][nt][1]+bb.y);
                float2 o1 = make_float2(acc[mt][nt][2]+bb.x, acc[mt][nt][3]+bb.y);
                *reinterpret_cast<float2*>(&out[(size_t)row*NV + col]) = o0;
                *reinterpret_cast<float2*>(&out[(size_t)(row+8)*NV + col]) = o1;
            }
        }
    }
}

// ============================== launch =======================================
extern "C" void kernel_launch(void* const* d_in, const int* in_sizes, int n_in,
                              void* d_out, int out_size){
    const float* enc    = (const float*)d_in[0];
    const int*   caps   = (const int*)  d_in[1];
    const float* W_enc  = (const float*)d_in[2];
    const float* b_enc  = (const float*)d_in[3];
    const float* W_dec  = (const float*)d_in[4];
    const float* b_dec  = (const float*)d_in[5];
    const float* W_full = (const float*)d_in[6];
    const float* emb    = (const float*)d_in[8];
    const float* W_ih   = (const float*)d_in[9];
    const float* b_ih   = (const float*)d_in[10];
    const float* W_hh   = (const float*)d_in[11];
    const float* b_hh   = (const float*)d_in[12];
    const float* W_fc   = (const float*)d_in[13];
    const float* b_fc   = (const float*)d_in[14];
    float* out = (float*)d_out;

    k_convW<<<dim3(938,16),256>>>(W_fc);
    k_att1<<<dim3(98,4),256>>>(enc, W_enc, b_enc);
    for (int t=0;t<NT;t++){
        k_lstm<<<32,256>>>(t, emb, caps, b_ih, b_hh);
        k_att2p<<<dim3(8,8,4),256>>>(W_dec);
        k_escore<<<dim3(32,7),128>>>(W_full, b_dec);
        k_ctx<<<32,256>>>(enc);
        k_gates<<<dim3(8,20),256>>>(W_ih, W_hh);
    }
    k_lstm<<<32,256>>>(NT, emb, caps, b_ih, b_hh);
    k_fc_mma<<<dim3(5,235),256>>>(b_fc, out);
}